// round 15
// baseline (speedup 1.0000x reference)
#include <cuda_runtime.h>
#include <cstdint>

// NetVLAD fused pool, 3-product BF16 mma.sync m16n8k16, sm_103a. Round 15.
// = Round 14 (Rn-only smem, PRMT stage-A frags, 3 CTA/SM) with SPLIT=8:
// grid 2048, 2 tiles/CTA -> 4.61 waves (7.7% tail vs 23% at SPLIT=4).

#define MMA_BF16(d0,d1,d2,d3, a0,a1,a2,a3, b0,b1) \
  asm volatile("mma.sync.aligned.m16n8k16.row.col.f32.bf16.bf16.f32 " \
      "{%0,%1,%2,%3},{%4,%5,%6,%7},{%8,%9},{%0,%1,%2,%3};" \
      : "+f"(d0),"+f"(d1),"+f"(d2),"+f"(d3) \
      : "r"(a0),"r"(a1),"r"(a2),"r"(a3),"r"(b0),"r"(b1))
#define CVT2(d, lo, hi) \
  asm("cvt.rn.satfinite.bf16x2.f32 %0, %1, %2;" : "=r"(d) : "f"(hi), "f"(lo))

__device__ __forceinline__ float lo16f(uint32_t x){ return __uint_as_float(x << 16); }
__device__ __forceinline__ float hi16f(uint32_t x){ return __uint_as_float(x & 0xFFFF0000u); }
__device__ __forceinline__ void pair2(float x, float y, uint32_t& H, uint32_t& L){
    CVT2(H, x, y);
    CVT2(L, x - lo16f(H), y - hi16f(H));
}

namespace {
constexpr int Nn = 2048, Cc = 64, Kk = 32;
constexpr int SPLIT = 8, NT = 128;
constexpr int TILES = (Nn / SPLIT) / NT;   // 2
constexpr int RNP = 72, WCP = 36, AKP = 68;
constexpr int O_RNH = 0;
constexpr int O_RNL = O_RNH + 64 * RNP;
constexpr int O_WCH = O_RNL + 64 * RNP;
constexpr int O_WCL = O_WCH + Kk * WCP;
constexpr int O_AKH = O_WCL + Kk * WCP;
constexpr int O_AKL = O_AKH + Kk * AKP;
constexpr int O_AS  = O_AKL + Kk * AKP;
constexpr int O_BS  = O_AS + 32;
constexpr int SMEM_BYTES = (O_BS + 32) * 4;    // 63,744 B -> 3 CTA/SM
}

__global__ void nv_zero(float4* __restrict__ out, int n4) {
    int i = blockIdx.x * blockDim.x + threadIdx.x;
    if (i < n4) out[i] = make_float4(0.f, 0.f, 0.f, 0.f);
}

__global__ __launch_bounds__(256, 3) void nv_tc(
    const float* __restrict__ R, const float* __restrict__ W,
    const float* __restrict__ bvec, const float* __restrict__ cent,
    float* __restrict__ out)
{
    extern __shared__ float sm[];
    uint32_t* RNH = (uint32_t*)(sm + O_RNH);
    uint32_t* RNL = (uint32_t*)(sm + O_RNL);
    uint32_t* WCH = (uint32_t*)(sm + O_WCH);
    uint32_t* WCL = (uint32_t*)(sm + O_WCL);
    uint32_t* AKH = (uint32_t*)(sm + O_AKH);
    uint32_t* AKL = (uint32_t*)(sm + O_AKL);
    float* asum_sm = sm + O_AS;
    float* bsm     = sm + O_BS;

    const int t = threadIdx.x;
    const int m = blockIdx.x >> 3;
    const int s = blockIdx.x & 7;
    const int w = t >> 5, lane = t & 31;
    const int g = lane >> 2, q = lane & 3;
    const bool evenlane = (lane & 4) == 0;

    if (t < 32) { asum_sm[t] = 0.f; bsm[t] = bvec[t]; }
    #pragma unroll
    for (int i = 0; i < 4; i++) {
        int idx = i * 256 + t, k = idx >> 5, cp = idx & 31;
        float2 wv = ((const float2*)W)[idx];
        uint32_t H, L; pair2(wv.x, wv.y, H, L);
        WCH[k * WCP + cp] = H; WCL[k * WCP + cp] = L;
    }

    const int kb = w & 1, cb0 = (w >> 1) * 16, rb = 16 * w;
    const int col4 = t & 15, rp0 = t >> 4;
    const uint32_t psel = (g & 1) ? 0x7632u : 0x5410u;
    const int npg  = (rb + g) >> 1;
    const int npg8 = (rb + g + 8) >> 1;

    float vA[2][4], asl[4][2];
    #pragma unroll
    for (int cb = 0; cb < 2; cb++)
        #pragma unroll
        for (int r = 0; r < 4; r++) vA[cb][r] = 0.f;
    #pragma unroll
    for (int nb = 0; nb < 4; nb++) asl[nb][0] = asl[nb][1] = 0.f;

    const float* Rbase = R + ((size_t)m * Nn + (size_t)s * (Nn / SPLIT)) * Cc;

    for (int tile = 0; tile < TILES; ++tile) {
        if (tile > 0) __syncthreads();
        const float4* Rg = (const float4*)(Rbase + (size_t)tile * NT * Cc);

        // load + split + store Rn (n-pair packed)
        #pragma unroll
        for (int j = 0; j < 4; j++) {
            const int rp = rp0 + 16 * j;
            float4 a = Rg[(2 * rp) * 16 + col4];
            float4 b = Rg[(2 * rp + 1) * 16 + col4];
            uint4 nh, nl;
            pair2(a.x, b.x, nh.x, nl.x);
            pair2(a.y, b.y, nh.y, nl.y);
            pair2(a.z, b.z, nh.z, nl.z);
            pair2(a.w, b.w, nh.w, nl.w);
            *(uint4*)(RNH + rp * RNP + 4 * col4) = nh;
            *(uint4*)(RNL + rp * RNP + 4 * col4) = nl;
        }
        __syncthreads();

        // Stage A: fragments from Rn via uint2 LDS + PRMT
        float dA[4][4];
        #pragma unroll
        for (int nb = 0; nb < 4; nb++) {
            float b0 = bsm[8 * nb + 2 * q], b1 = bsm[8 * nb + 2 * q + 1];
            dA[nb][0] = b0; dA[nb][1] = b1; dA[nb][2] = b0; dA[nb][3] = b1;
        }
        #pragma unroll
        for (int ch = 0; ch < 4; ch++) {
            const int ci = 16 * ch + 2 * q;
            uint2 h0 = *(uint2*)(RNH + npg  * RNP + ci);
            uint2 l0 = *(uint2*)(RNL + npg  * RNP + ci);
            uint2 h1 = *(uint2*)(RNH + npg8 * RNP + ci);
            uint2 l1 = *(uint2*)(RNL + npg8 * RNP + ci);
            uint2 h2 = *(uint2*)(RNH + npg  * RNP + ci + 8);
            uint2 l2 = *(uint2*)(RNL + npg  * RNP + ci + 8);
            uint2 h3 = *(uint2*)(RNH + npg8 * RNP + ci + 8);
            uint2 l3 = *(uint2*)(RNL + npg8 * RNP + ci + 8);
            uint32_t Ah0 = __byte_perm(h0.x, h0.y, psel), Al0 = __byte_perm(l0.x, l0.y, psel);
            uint32_t Ah1 = __byte_perm(h1.x, h1.y, psel), Al1 = __byte_perm(l1.x, l1.y, psel);
            uint32_t Ah2 = __byte_perm(h2.x, h2.y, psel), Al2 = __byte_perm(l2.x, l2.y, psel);
            uint32_t Ah3 = __byte_perm(h3.x, h3.y, psel), Al3 = __byte_perm(l3.x, l3.y, psel);
            #pragma unroll
            for (int nb = 0; nb < 4; nb++) {
                const int kr = (8 * nb + g) * WCP + 8 * ch;
                uint32_t Bh0 = WCH[kr + q], Bh1 = WCH[kr + 4 + q];
                uint32_t Bl0 = WCL[kr + q], Bl1 = WCL[kr + 4 + q];
                MMA_BF16(dA[nb][0],dA[nb][1],dA[nb][2],dA[nb][3], Ah0,Ah1,Ah2,Ah3, Bh0,Bh1);
                MMA_BF16(dA[nb][0],dA[nb][1],dA[nb][2],dA[nb][3], Ah0,Ah1,Ah2,Ah3, Bl0,Bl1);
                MMA_BF16(dA[nb][0],dA[nb][1],dA[nb][2],dA[nb][3], Al0,Al1,Al2,Al3, Bh0,Bh1);
            }
        }

        // softmax over k (rows rb+g, rb+g+8)
        float mx0 = -1e30f, mx1 = -1e30f;
        #pragma unroll
        for (int nb = 0; nb < 4; nb++) {
            mx0 = fmaxf(mx0, fmaxf(dA[nb][0], dA[nb][1]));
            mx1 = fmaxf(mx1, fmaxf(dA[nb][2], dA[nb][3]));
        }
        mx0 = fmaxf(mx0, __shfl_xor_sync(~0u, mx0, 1));
        mx0 = fmaxf(mx0, __shfl_xor_sync(~0u, mx0, 2));
        mx1 = fmaxf(mx1, __shfl_xor_sync(~0u, mx1, 1));
        mx1 = fmaxf(mx1, __shfl_xor_sync(~0u, mx1, 2));
        float s0 = 0.f, s1 = 0.f;
        #pragma unroll
        for (int nb = 0; nb < 4; nb++) {
            dA[nb][0] = __expf(dA[nb][0] - mx0);
            dA[nb][1] = __expf(dA[nb][1] - mx0);
            dA[nb][2] = __expf(dA[nb][2] - mx1);
            dA[nb][3] = __expf(dA[nb][3] - mx1);
            s0 += dA[nb][0] + dA[nb][1];
            s1 += dA[nb][2] + dA[nb][3];
        }
        s0 += __shfl_xor_sync(~0u, s0, 1); s0 += __shfl_xor_sync(~0u, s0, 2);
        s1 += __shfl_xor_sync(~0u, s1, 1); s1 += __shfl_xor_sync(~0u, s1, 2);
        const float inv0 = __fdividef(1.f, s0), inv1 = __fdividef(1.f, s1);
        #pragma unroll
        for (int nb = 0; nb < 4; nb++) {
            #pragma unroll
            for (int j = 0; j < 2; j++) {
                const int k = 8 * nb + 2 * q + j;
                float p0 = dA[nb][j] * inv0, p1 = dA[nb][j + 2] * inv1;
                asl[nb][j] += p0 + p1;
                float o0 = __shfl_xor_sync(~0u, p0, 4);
                float o1 = __shfl_xor_sync(~0u, p1, 4);
                if (evenlane) {
                    const int np0 = (rb + g) >> 1, np1 = (rb + g + 8) >> 1;
                    uint32_t H, L;
                    pair2(p0, o0, H, L);
                    AKH[k * AKP + np0] = H; AKL[k * AKP + np0] = L;
                    pair2(p1, o1, H, L);
                    AKH[k * AKP + np1] = H; AKL[k * AKP + np1] = L;
                }
            }
        }
        __syncthreads();

        // Stage B: V[k][c] += A'[k][n]*R[n][c]
        #pragma unroll 4
        for (int ch = 0; ch < 8; ch++) {
            const int npb = 8 * ch;
            const int a0i = (16 * kb + g) * AKP + npb;
            const int a1i = (16 * kb + g + 8) * AKP + npb;
            uint32_t Ph0 = AKH[a0i + q],     Pl0 = AKL[a0i + q];
            uint32_t Ph1 = AKH[a1i + q],     Pl1 = AKL[a1i + q];
            uint32_t Ph2 = AKH[a0i + 4 + q], Pl2 = AKL[a0i + 4 + q];
            uint32_t Ph3 = AKH[a1i + 4 + q], Pl3 = AKL[a1i + 4 + q];
            #pragma unroll
            for (int cb = 0; cb < 2; cb++) {
                const int c0 = cb0 + 8 * cb;
                const int b0i = (npb + q) * RNP + c0 + g;
                const int b1i = (npb + 4 + q) * RNP + c0 + g;
                uint32_t Rh0 = RNH[b0i], Rl0 = RNL[b0i];
                uint32_t Rh1 = RNH[b1i], Rl1 = RNL[b1i];
                MMA_BF16(vA[cb][0],vA[cb][1],vA[cb][2],vA[cb][3], Ph0,Ph1,Ph2,Ph3, Rh0,Rh1);
                MMA_BF16(vA[cb][0],vA[cb][1],vA[cb][2],vA[cb][3], Ph0,Ph1,Ph2,Ph3, Rl0,Rl1);
                MMA_BF16(vA[cb][0],vA[cb][1],vA[cb][2],vA[cb][3], Pl0,Pl1,Pl2,Pl3, Rh0,Rh1);
            }
        }
    }

    // asum reduce + epilogue
    #pragma unroll
    for (int nb = 0; nb < 4; nb++)
        #pragma unroll
        for (int j = 0; j < 2; j++) {
            float v = asl[nb][j];
            v += __shfl_xor_sync(~0u, v, 4);
            v += __shfl_xor_sync(~0u, v, 8);
            v += __shfl_xor_sync(~0u, v, 16);
            if (g == 0) atomicAdd(&asum_sm[8 * nb + 2 * q + j], v);
        }
    __syncthreads();

    float* outm = out + (size_t)m * Kk * Cc;
    const int k0 = 16 * kb + g, k1 = k0 + 8;
    const float as0 = asum_sm[k0], as1 = asum_sm[k1];
    #pragma unroll
    for (int cb = 0; cb < 2; cb++) {
        const int c = cb0 + 8 * cb + 2 * q;
        const float2 c0v = *(const float2*)(cent + k0 * 64 + c);
        const float2 c1v = *(const float2*)(cent + k1 * 64 + c);
        atomicAdd(outm + k0 * 64 + c,     vA[cb][0] - as0 * c0v.x);
        atomicAdd(outm + k0 * 64 + c + 1, vA[cb][1] - as0 * c0v.y);
        atomicAdd(outm + k1 * 64 + c,     vA[cb][2] - as1 * c1v.x);
        atomicAdd(outm + k1 * 64 + c + 1, vA[cb][3] - as1 * c1v.y);
    }
}

extern "C" void kernel_launch(void* const* d_in, const int* in_sizes, int n_in,
                              void* d_out, int out_size) {
    const float* R = (const float*)d_in[0];
    const float* W = (const float*)d_in[1];
    const float* b = (const float*)d_in[2];
    const float* cent = (const float*)d_in[3];
    float* out = (float*)d_out;
    cudaFuncSetAttribute(nv_tc, cudaFuncAttributeMaxDynamicSharedMemorySize, SMEM_BYTES);
    int n4 = out_size / 4;
    nv_zero<<<(n4 + 255) / 256, 256>>>((float4*)out, n4);
    nv_tc<<<256 * SPLIT, 256, SMEM_BYTES>>>(R, W, b, cent, out);
}

// round 16
// speedup vs baseline: 1.0985x; 1.0985x over previous
#include <cuda_runtime.h>
#include <cstdint>

// NetVLAD fused pool, BF16 mma.sync m16n8k16, sm_103a. Round 16.
// = Round 14 (Rn-only smem, PRMT stage-A frags, 3 CTA/SM, SPLIT=4) with
// stage A reduced to 2 products (hh + hl; lh dropped, err ~3e-5) -> Al loads,
// PRMTs and 16 HMMAs removed per warp-tile. Stage B keeps 3 products.

#define MMA_BF16(d0,d1,d2,d3, a0,a1,a2,a3, b0,b1) \
  asm volatile("mma.sync.aligned.m16n8k16.row.col.f32.bf16.bf16.f32 " \
      "{%0,%1,%2,%3},{%4,%5,%6,%7},{%8,%9},{%0,%1,%2,%3};" \
      : "+f"(d0),"+f"(d1),"+f"(d2),"+f"(d3) \
      : "r"(a0),"r"(a1),"r"(a2),"r"(a3),"r"(b0),"r"(b1))
#define CVT2(d, lo, hi) \
  asm("cvt.rn.satfinite.bf16x2.f32 %0, %1, %2;" : "=r"(d) : "f"(hi), "f"(lo))

__device__ __forceinline__ float lo16f(uint32_t x){ return __uint_as_float(x << 16); }
__device__ __forceinline__ float hi16f(uint32_t x){ return __uint_as_float(x & 0xFFFF0000u); }
__device__ __forceinline__ void pair2(float x, float y, uint32_t& H, uint32_t& L){
    CVT2(H, x, y);
    CVT2(L, x - lo16f(H), y - hi16f(H));
}

namespace {
constexpr int Nn = 2048, Cc = 64, Kk = 32;
constexpr int SPLIT = 4, NT = 128;
constexpr int TILES = (Nn / SPLIT) / NT;   // 4
constexpr int RNP = 72, WCP = 36, AKP = 68;
constexpr int O_RNH = 0;
constexpr int O_RNL = O_RNH + 64 * RNP;
constexpr int O_WCH = O_RNL + 64 * RNP;
constexpr int O_WCL = O_WCH + Kk * WCP;
constexpr int O_AKH = O_WCL + Kk * WCP;
constexpr int O_AKL = O_AKH + Kk * AKP;
constexpr int O_AS  = O_AKL + Kk * AKP;
constexpr int O_BS  = O_AS + 32;
constexpr int SMEM_BYTES = (O_BS + 32) * 4;    // 63,744 B -> 3 CTA/SM
}

__global__ void nv_zero(float4* __restrict__ out, int n4) {
    int i = blockIdx.x * blockDim.x + threadIdx.x;
    if (i < n4) out[i] = make_float4(0.f, 0.f, 0.f, 0.f);
}

__global__ __launch_bounds__(256, 3) void nv_tc(
    const float* __restrict__ R, const float* __restrict__ W,
    const float* __restrict__ bvec, const float* __restrict__ cent,
    float* __restrict__ out)
{
    extern __shared__ float sm[];
    uint32_t* RNH = (uint32_t*)(sm + O_RNH);
    uint32_t* RNL = (uint32_t*)(sm + O_RNL);
    uint32_t* WCH = (uint32_t*)(sm + O_WCH);
    uint32_t* WCL = (uint32_t*)(sm + O_WCL);
    uint32_t* AKH = (uint32_t*)(sm + O_AKH);
    uint32_t* AKL = (uint32_t*)(sm + O_AKL);
    float* asum_sm = sm + O_AS;
    float* bsm     = sm + O_BS;

    const int t = threadIdx.x;
    const int m = blockIdx.x >> 2;
    const int s = blockIdx.x & 3;
    const int w = t >> 5, lane = t & 31;
    const int g = lane >> 2, q = lane & 3;
    const bool evenlane = (lane & 4) == 0;

    if (t < 32) { asum_sm[t] = 0.f; bsm[t] = bvec[t]; }
    #pragma unroll
    for (int i = 0; i < 4; i++) {
        int idx = i * 256 + t, k = idx >> 5, cp = idx & 31;
        float2 wv = ((const float2*)W)[idx];
        uint32_t H, L; pair2(wv.x, wv.y, H, L);
        WCH[k * WCP + cp] = H; WCL[k * WCP + cp] = L;
    }

    const int kb = w & 1, cb0 = (w >> 1) * 16, rb = 16 * w;
    const int col4 = t & 15, rp0 = t >> 4;
    const uint32_t psel = (g & 1) ? 0x7632u : 0x5410u;
    const int npg  = (rb + g) >> 1;
    const int npg8 = (rb + g + 8) >> 1;

    float vA[2][4], asl[4][2];
    #pragma unroll
    for (int cb = 0; cb < 2; cb++)
        #pragma unroll
        for (int r = 0; r < 4; r++) vA[cb][r] = 0.f;
    #pragma unroll
    for (int nb = 0; nb < 4; nb++) asl[nb][0] = asl[nb][1] = 0.f;

    const float* Rbase = R + ((size_t)m * Nn + (size_t)s * (Nn / SPLIT)) * Cc;

    for (int tile = 0; tile < TILES; ++tile) {
        if (tile > 0) __syncthreads();
        const float4* Rg = (const float4*)(Rbase + (size_t)tile * NT * Cc);

        // load + split + store Rn (n-pair packed)
        #pragma unroll
        for (int j = 0; j < 4; j++) {
            const int rp = rp0 + 16 * j;
            float4 a = Rg[(2 * rp) * 16 + col4];
            float4 b = Rg[(2 * rp + 1) * 16 + col4];
            uint4 nh, nl;
            pair2(a.x, b.x, nh.x, nl.x);
            pair2(a.y, b.y, nh.y, nl.y);
            pair2(a.z, b.z, nh.z, nl.z);
            pair2(a.w, b.w, nh.w, nl.w);
            *(uint4*)(RNH + rp * RNP + 4 * col4) = nh;
            *(uint4*)(RNL + rp * RNP + 4 * col4) = nl;
        }
        __syncthreads();

        // Stage A (2-product): fragments from RNH via uint2 LDS + PRMT
        float dA[4][4];
        #pragma unroll
        for (int nb = 0; nb < 4; nb++) {
            float b0 = bsm[8 * nb + 2 * q], b1 = bsm[8 * nb + 2 * q + 1];
            dA[nb][0] = b0; dA[nb][1] = b1; dA[nb][2] = b0; dA[nb][3] = b1;
        }
        #pragma unroll
        for (int ch = 0; ch < 4; ch++) {
            const int ci = 16 * ch + 2 * q;
            uint2 h0 = *(uint2*)(RNH + npg  * RNP + ci);
            uint2 h1 = *(uint2*)(RNH + npg8 * RNP + ci);
            uint2 h2 = *(uint2*)(RNH + npg  * RNP + ci + 8);
            uint2 h3 = *(uint2*)(RNH + npg8 * RNP + ci + 8);
            uint32_t Ah0 = __byte_perm(h0.x, h0.y, psel);
            uint32_t Ah1 = __byte_perm(h1.x, h1.y, psel);
            uint32_t Ah2 = __byte_perm(h2.x, h2.y, psel);
            uint32_t Ah3 = __byte_perm(h3.x, h3.y, psel);
            #pragma unroll
            for (int nb = 0; nb < 4; nb++) {
                const int kr = (8 * nb + g) * WCP + 8 * ch;
                uint32_t Bh0 = WCH[kr + q], Bh1 = WCH[kr + 4 + q];
                uint32_t Bl0 = WCL[kr + q], Bl1 = WCL[kr + 4 + q];
                MMA_BF16(dA[nb][0],dA[nb][1],dA[nb][2],dA[nb][3], Ah0,Ah1,Ah2,Ah3, Bh0,Bh1);
                MMA_BF16(dA[nb][0],dA[nb][1],dA[nb][2],dA[nb][3], Ah0,Ah1,Ah2,Ah3, Bl0,Bl1);
            }
        }

        // softmax over k (rows rb+g, rb+g+8)
        float mx0 = -1e30f, mx1 = -1e30f;
        #pragma unroll
        for (int nb = 0; nb < 4; nb++) {
            mx0 = fmaxf(mx0, fmaxf(dA[nb][0], dA[nb][1]));
            mx1 = fmaxf(mx1, fmaxf(dA[nb][2], dA[nb][3]));
        }
        mx0 = fmaxf(mx0, __shfl_xor_sync(~0u, mx0, 1));
        mx0 = fmaxf(mx0, __shfl_xor_sync(~0u, mx0, 2));
        mx1 = fmaxf(mx1, __shfl_xor_sync(~0u, mx1, 1));
        mx1 = fmaxf(mx1, __shfl_xor_sync(~0u, mx1, 2));
        float s0 = 0.f, s1 = 0.f;
        #pragma unroll
        for (int nb = 0; nb < 4; nb++) {
            dA[nb][0] = __expf(dA[nb][0] - mx0);
            dA[nb][1] = __expf(dA[nb][1] - mx0);
            dA[nb][2] = __expf(dA[nb][2] - mx1);
            dA[nb][3] = __expf(dA[nb][3] - mx1);
            s0 += dA[nb][0] + dA[nb][1];
            s1 += dA[nb][2] + dA[nb][3];
        }
        s0 += __shfl_xor_sync(~0u, s0, 1); s0 += __shfl_xor_sync(~0u, s0, 2);
        s1 += __shfl_xor_sync(~0u, s1, 1); s1 += __shfl_xor_sync(~0u, s1, 2);
        const float inv0 = __fdividef(1.f, s0), inv1 = __fdividef(1.f, s1);
        #pragma unroll
        for (int nb = 0; nb < 4; nb++) {
            #pragma unroll
            for (int j = 0; j < 2; j++) {
                const int k = 8 * nb + 2 * q + j;
                float p0 = dA[nb][j] * inv0, p1 = dA[nb][j + 2] * inv1;
                asl[nb][j] += p0 + p1;
                float o0 = __shfl_xor_sync(~0u, p0, 4);
                float o1 = __shfl_xor_sync(~0u, p1, 4);
                if (evenlane) {
                    const int np0 = (rb + g) >> 1, np1 = (rb + g + 8) >> 1;
                    uint32_t H, L;
                    pair2(p0, o0, H, L);
                    AKH[k * AKP + np0] = H; AKL[k * AKP + np0] = L;
                    pair2(p1, o1, H, L);
                    AKH[k * AKP + np1] = H; AKL[k * AKP + np1] = L;
                }
            }
        }
        __syncthreads();

        // Stage B (3-product): V[k][c] += A'[k][n]*R[n][c]
        #pragma unroll 8
        for (int ch = 0; ch < 8; ch++) {
            const int npb = 8 * ch;
            const int a0i = (16 * kb + g) * AKP + npb;
            const int a1i = (16 * kb + g + 8) * AKP + npb;
            uint32_t Ph0 = AKH[a0i + q],     Pl0 = AKL[a0i + q];
            uint32_t Ph1 = AKH[a1i + q],     Pl1 = AKL[a1i + q];
            uint32_t Ph2 = AKH[a0i + 4 + q], Pl2 = AKL[a0i + 4 + q];
            uint32_t Ph3 = AKH[a1i + 4 + q], Pl3 = AKL[a1i + 4 + q];
            #pragma unroll
            for (int cb = 0; cb < 2; cb++) {
                const int c0 = cb0 + 8 * cb;
                const int b0i = (npb + q) * RNP + c0 + g;
                const int b1i = (npb + 4 + q) * RNP + c0 + g;
                uint32_t Rh0 = RNH[b0i], Rl0 = RNL[b0i];
                uint32_t Rh1 = RNH[b1i], Rl1 = RNL[b1i];
                MMA_BF16(vA[cb][0],vA[cb][1],vA[cb][2],vA[cb][3], Ph0,Ph1,Ph2,Ph3, Rh0,Rh1);
                MMA_BF16(vA[cb][0],vA[cb][1],vA[cb][2],vA[cb][3], Ph0,Ph1,Ph2,Ph3, Rl0,Rl1);
                MMA_BF16(vA[cb][0],vA[cb][1],vA[cb][2],vA[cb][3], Pl0,Pl1,Pl2,Pl3, Rh0,Rh1);
            }
        }
    }

    // asum reduce + epilogue
    #pragma unroll
    for (int nb = 0; nb < 4; nb++)
        #pragma unroll
        for (int j = 0; j < 2; j++) {
            float v = asl[nb][j];
            v += __shfl_xor_sync(~0u, v, 4);
            v += __shfl_xor_sync(~0u, v, 8);
            v += __shfl_xor_sync(~0u, v, 16);
            if (g == 0) atomicAdd(&asum_sm[8 * nb + 2 * q + j], v);
        }
    __syncthreads();

    float* outm = out + (size_t)m * Kk * Cc;
    const int k0 = 16 * kb + g, k1 = k0 + 8;
    const float as0 = asum_sm[k0], as1 = asum_sm[k1];
    #pragma unroll
    for (int cb = 0; cb < 2; cb++) {
        const int c = cb0 + 8 * cb + 2 * q;
        const float2 c0v = *(const float2*)(cent + k0 * 64 + c);
        const float2 c1v = *(const float2*)(cent + k1 * 64 + c);
        atomicAdd(outm + k0 * 64 + c,     vA[cb][0] - as0 * c0v.x);
        atomicAdd(outm + k0 * 64 + c + 1, vA[cb][1] - as0 * c0v.y);
        atomicAdd(outm + k1 * 64 + c,     vA[cb][2] - as1 * c1v.x);
        atomicAdd(outm + k1 * 64 + c + 1, vA[cb][3] - as1 * c1v.y);
    }
}

extern "C" void kernel_launch(void* const* d_in, const int* in_sizes, int n_in,
                              void* d_out, int out_size) {
    const float* R = (const float*)d_in[0];
    const float* W = (const float*)d_in[1];
    const float* b = (const float*)d_in[2];
    const float* cent = (const float*)d_in[3];
    float* out = (float*)d_out;
    cudaFuncSetAttribute(nv_tc, cudaFuncAttributeMaxDynamicSharedMemorySize, SMEM_BYTES);
    int n4 = out_size / 4;
    nv_zero<<<(n4 + 255) / 256, 256>>>((float4*)out, n4);
    nv_tc<<<256 * SPLIT, 256, SMEM_BYTES>>>(R, W, b, cent, out);
}

// round 17
// speedup vs baseline: 1.1235x; 1.0228x over previous
#include <cuda_runtime.h>
#include <cstdint>

// NetVLAD fused pool, BF16 mma.sync m16n8k16, sm_103a. Round 17.
// = R16 (2-product stage A, 3-product stage B, 3 CTA/SM, SPLIT=4) plus:
// (1) A' permuted columns (AKP=72): stage-B A-loads as LDS.64, A' STS as STS.64;
// (2) warp-local loader rows -> __syncwarp before stage A, 2 barriers/tile.

#define MMA_BF16(d0,d1,d2,d3, a0,a1,a2,a3, b0,b1) \
  asm volatile("mma.sync.aligned.m16n8k16.row.col.f32.bf16.bf16.f32 " \
      "{%0,%1,%2,%3},{%4,%5,%6,%7},{%8,%9},{%0,%1,%2,%3};" \
      : "+f"(d0),"+f"(d1),"+f"(d2),"+f"(d3) \
      : "r"(a0),"r"(a1),"r"(a2),"r"(a3),"r"(b0),"r"(b1))
#define CVT2(d, lo, hi) \
  asm("cvt.rn.satfinite.bf16x2.f32 %0, %1, %2;" : "=r"(d) : "f"(hi), "f"(lo))

__device__ __forceinline__ float lo16f(uint32_t x){ return __uint_as_float(x << 16); }
__device__ __forceinline__ float hi16f(uint32_t x){ return __uint_as_float(x & 0xFFFF0000u); }
__device__ __forceinline__ void pair2(float x, float y, uint32_t& H, uint32_t& L){
    CVT2(H, x, y);
    CVT2(L, x - lo16f(H), y - hi16f(H));
}

namespace {
constexpr int Nn = 2048, Cc = 64, Kk = 32;
constexpr int SPLIT = 4, NT = 128;
constexpr int TILES = (Nn / SPLIT) / NT;   // 4
constexpr int RNP = 72, WCP = 36, AKP = 72;
constexpr int O_RNH = 0;
constexpr int O_RNL = O_RNH + 64 * RNP;        // 4608
constexpr int O_WCH = O_RNL + 64 * RNP;        // 9216
constexpr int O_WCL = O_WCH + Kk * WCP;        // 10368
constexpr int O_AKH = O_WCL + Kk * WCP;        // 11520
constexpr int O_AKL = O_AKH + Kk * AKP;        // 13824
constexpr int O_AS  = O_AKL + Kk * AKP;        // 16128
constexpr int O_BS  = O_AS + 32;
constexpr int SMEM_BYTES = (O_BS + 32) * 4;    // 64,768 B -> 3 CTA/SM
}

__global__ void nv_zero(float4* __restrict__ out, int n4) {
    int i = blockIdx.x * blockDim.x + threadIdx.x;
    if (i < n4) out[i] = make_float4(0.f, 0.f, 0.f, 0.f);
}

__global__ __launch_bounds__(256, 3) void nv_tc(
    const float* __restrict__ R, const float* __restrict__ W,
    const float* __restrict__ bvec, const float* __restrict__ cent,
    float* __restrict__ out)
{
    extern __shared__ float sm[];
    uint32_t* RNH = (uint32_t*)(sm + O_RNH);
    uint32_t* RNL = (uint32_t*)(sm + O_RNL);
    uint32_t* WCH = (uint32_t*)(sm + O_WCH);
    uint32_t* WCL = (uint32_t*)(sm + O_WCL);
    uint32_t* AKH = (uint32_t*)(sm + O_AKH);
    uint32_t* AKL = (uint32_t*)(sm + O_AKL);
    float* asum_sm = sm + O_AS;
    float* bsm     = sm + O_BS;

    const int t = threadIdx.x;
    const int m = blockIdx.x >> 2;
    const int s = blockIdx.x & 3;
    const int w = t >> 5, lane = t & 31;
    const int g = lane >> 2, q = lane & 3;
    const bool evenlane = (lane & 4) == 0;

    if (t < 32) { asum_sm[t] = 0.f; bsm[t] = bvec[t]; }
    #pragma unroll
    for (int i = 0; i < 4; i++) {
        int idx = i * 256 + t, k = idx >> 5, cp = idx & 31;
        float2 wv = ((const float2*)W)[idx];
        uint32_t H, L; pair2(wv.x, wv.y, H, L);
        WCH[k * WCP + cp] = H; WCL[k * WCP + cp] = L;
    }
    // W visibility for stage A is covered by the loop-top __syncthreads().

    const int kb = w & 1, cb0 = (w >> 1) * 16, rb = 16 * w;
    const int L4 = lane >> 4, c4 = lane & 15;   // warp-local loader mapping
    const uint32_t psel = (g & 1) ? 0x7632u : 0x5410u;
    const int npg  = (rb + g) >> 1;
    const int npg8 = (rb + g + 8) >> 1;

    float vA[2][4], asl[4][2];
    #pragma unroll
    for (int cb = 0; cb < 2; cb++)
        #pragma unroll
        for (int r = 0; r < 4; r++) vA[cb][r] = 0.f;
    #pragma unroll
    for (int nb = 0; nb < 4; nb++) asl[nb][0] = asl[nb][1] = 0.f;

    const float* Rbase = R + ((size_t)m * Nn + (size_t)s * (Nn / SPLIT)) * Cc;

    for (int tile = 0; tile < TILES; ++tile) {
        __syncthreads();   // prior stage B done with Rn/AK (tile0: covers W STS)
        const float4* Rg = (const float4*)(Rbase + (size_t)tile * NT * Cc);

        // ---- load + split + store Rn: warp w owns rowpairs 8w..8w+7
        #pragma unroll
        for (int j = 0; j < 4; j++) {
            const int rp = 8 * w + 2 * j + L4;
            float4 a = Rg[(2 * rp) * 16 + c4];
            float4 b = Rg[(2 * rp + 1) * 16 + c4];
            uint4 nh, nl;
            pair2(a.x, b.x, nh.x, nl.x);
            pair2(a.y, b.y, nh.y, nl.y);
            pair2(a.z, b.z, nh.z, nl.z);
            pair2(a.w, b.w, nh.w, nl.w);
            *(uint4*)(RNH + rp * RNP + 4 * c4) = nh;
            *(uint4*)(RNL + rp * RNP + 4 * c4) = nl;
        }
        __syncwarp();      // stage A reads only this warp's rows

        // ---- Stage A (2-product): fragments from RNH via uint2 LDS + PRMT
        float dA[4][4];
        #pragma unroll
        for (int nb = 0; nb < 4; nb++) {
            float b0 = bsm[8 * nb + 2 * q], b1 = bsm[8 * nb + 2 * q + 1];
            dA[nb][0] = b0; dA[nb][1] = b1; dA[nb][2] = b0; dA[nb][3] = b1;
        }
        #pragma unroll
        for (int ch = 0; ch < 4; ch++) {
            const int ci = 16 * ch + 2 * q;
            uint2 h0 = *(uint2*)(RNH + npg  * RNP + ci);
            uint2 h1 = *(uint2*)(RNH + npg8 * RNP + ci);
            uint2 h2 = *(uint2*)(RNH + npg  * RNP + ci + 8);
            uint2 h3 = *(uint2*)(RNH + npg8 * RNP + ci + 8);
            uint32_t Ah0 = __byte_perm(h0.x, h0.y, psel);
            uint32_t Ah1 = __byte_perm(h1.x, h1.y, psel);
            uint32_t Ah2 = __byte_perm(h2.x, h2.y, psel);
            uint32_t Ah3 = __byte_perm(h3.x, h3.y, psel);
            #pragma unroll
            for (int nb = 0; nb < 4; nb++) {
                const int kr = (8 * nb + g) * WCP + 8 * ch;
                uint32_t Bh0 = WCH[kr + q], Bh1 = WCH[kr + 4 + q];
                uint32_t Bl0 = WCL[kr + q], Bl1 = WCL[kr + 4 + q];
                MMA_BF16(dA[nb][0],dA[nb][1],dA[nb][2],dA[nb][3], Ah0,Ah1,Ah2,Ah3, Bh0,Bh1);
                MMA_BF16(dA[nb][0],dA[nb][1],dA[nb][2],dA[nb][3], Ah0,Ah1,Ah2,Ah3, Bl0,Bl1);
            }
        }

        // ---- softmax over k (rows rb+g, rb+g+8)
        float mx0 = -1e30f, mx1 = -1e30f;
        #pragma unroll
        for (int nb = 0; nb < 4; nb++) {
            mx0 = fmaxf(mx0, fmaxf(dA[nb][0], dA[nb][1]));
            mx1 = fmaxf(mx1, fmaxf(dA[nb][2], dA[nb][3]));
        }
        mx0 = fmaxf(mx0, __shfl_xor_sync(~0u, mx0, 1));
        mx0 = fmaxf(mx0, __shfl_xor_sync(~0u, mx0, 2));
        mx1 = fmaxf(mx1, __shfl_xor_sync(~0u, mx1, 1));
        mx1 = fmaxf(mx1, __shfl_xor_sync(~0u, mx1, 2));
        float s0 = 0.f, s1 = 0.f;
        #pragma unroll
        for (int nb = 0; nb < 4; nb++) {
            dA[nb][0] = __expf(dA[nb][0] - mx0);
            dA[nb][1] = __expf(dA[nb][1] - mx0);
            dA[nb][2] = __expf(dA[nb][2] - mx1);
            dA[nb][3] = __expf(dA[nb][3] - mx1);
            s0 += dA[nb][0] + dA[nb][1];
            s1 += dA[nb][2] + dA[nb][3];
        }
        s0 += __shfl_xor_sync(~0u, s0, 1); s0 += __shfl_xor_sync(~0u, s0, 2);
        s1 += __shfl_xor_sync(~0u, s1, 1); s1 += __shfl_xor_sync(~0u, s1, 2);
        const float inv0 = __fdividef(1.f, s0), inv1 = __fdividef(1.f, s1);
        #pragma unroll
        for (int nb = 0; nb < 4; nb++) {
            #pragma unroll
            for (int j = 0; j < 2; j++) {
                const int k = 8 * nb + 2 * q + j;
                float p0 = dA[nb][j] * inv0, p1 = dA[nb][j + 2] * inv1;
                asl[nb][j] += p0 + p1;
                float o0 = __shfl_xor_sync(~0u, p0, 4);
                float o1 = __shfl_xor_sync(~0u, p1, 4);
                if (evenlane) {
                    // permuted col: np0=8w+g/2 -> sc=8w+g ; np1=np0+4 -> sc+1
                    const int sc = k * AKP + 8 * w + g;
                    uint32_t H0, L0, H1, L1;
                    pair2(p0, o0, H0, L0);
                    pair2(p1, o1, H1, L1);
                    *(uint2*)(AKH + sc) = make_uint2(H0, H1);
                    *(uint2*)(AKL + sc) = make_uint2(L0, L1);
                }
            }
        }
        __syncthreads();   // A' + all warps' Rn visible for stage B

        // ---- Stage B (3-product): V[k][c] += A'[k][n]*R[n][c]
        #pragma unroll 8
        for (int ch = 0; ch < 8; ch++) {
            const int npb = 8 * ch;
            // permuted col: kpair q -> sc npb+2q ; kpair q+4 -> +1 (one LDS.64)
            const int a0i = (16 * kb + g) * AKP + npb + 2 * q;
            const int a1i = (16 * kb + g + 8) * AKP + npb + 2 * q;
            uint2 PH0 = *(uint2*)(AKH + a0i);   // {a0, a2}
            uint2 PH1 = *(uint2*)(AKH + a1i);   // {a1, a3}
            uint2 PL0 = *(uint2*)(AKL + a0i);
            uint2 PL1 = *(uint2*)(AKL + a1i);
            #pragma unroll
            for (int cb = 0; cb < 2; cb++) {
                const int c0 = cb0 + 8 * cb;
                const int b0i = (npb + q) * RNP + c0 + g;
                const int b1i = (npb + 4 + q) * RNP + c0 + g;
                uint32_t Rh0 = RNH[b0i], Rl0 = RNL[b0i];
                uint32_t Rh1 = RNH[b1i], Rl1 = RNL[b1i];
                MMA_BF16(vA[cb][0],vA[cb][1],vA[cb][2],vA[cb][3],
                         PH0.x,PH1.x,PH0.y,PH1.y, Rh0,Rh1);
                MMA_BF16(vA[cb][0],vA[cb][1],vA[cb][2],vA[cb][3],
                         PH0.x,PH1.x,PH0.y,PH1.y, Rl0,Rl1);
                MMA_BF16(vA[cb][0],vA[cb][1],vA[cb][2],vA[cb][3],
                         PL0.x,PL1.x,PL0.y,PL1.y, Rh0,Rh1);
            }
        }
    }

    // ---- asum reduce + epilogue
    #pragma unroll
    for (int nb = 0; nb < 4; nb++)
        #pragma unroll
        for (int j = 0; j < 2; j++) {
            float v = asl[nb][j];
            v += __shfl_xor_sync(~0u, v, 4);
            v += __shfl_xor_sync(~0u, v, 8);
            v += __shfl_xor_sync(~0u, v, 16);
            if (g == 0) atomicAdd(&asum_sm[8 * nb + 2 * q + j], v);
        }
    __syncthreads();

    float* outm = out + (size_t)m * Kk * Cc;
    const int k0 = 16 * kb + g, k1 = k0 + 8;
    const float as0 = asum_sm[k0], as1 = asum_sm[k1];
    #pragma unroll
    for (int cb = 0; cb < 2; cb++) {
        const int c = cb0 + 8 * cb + 2 * q;
        const float2 c0v = *(const float2*)(cent + k0 * 64 + c);
        const float2 c1v = *(const float2*)(cent + k1 * 64 + c);
        atomicAdd(outm + k0 * 64 + c,     vA[cb][0] - as0 * c0v.x);
        atomicAdd(outm + k0 * 64 + c + 1, vA[cb][1] - as0 * c0v.y);
        atomicAdd(outm + k1 * 64 + c,     vA[cb][2] - as1 * c1v.x);
        atomicAdd(outm + k1 * 64 + c + 1, vA[cb][3] - as1 * c1v.y);
    }
}

extern "C" void kernel_launch(void* const* d_in, const int* in_sizes, int n_in,
                              void* d_out, int out_size) {
    const float* R = (const float*)d_in[0];
    const float* W = (const float*)d_in[1];
    const float* b = (const float*)d_in[2];
    const float* cent = (const float*)d_in[3];
    float* out = (float*)d_out;
    cudaFuncSetAttribute(nv_tc, cudaFuncAttributeMaxDynamicSharedMemorySize, SMEM_BYTES);
    int n4 = out_size / 4;
    nv_zero<<<(n4 + 255) / 256, 256>>>((float4*)out, n4);
    nv_tc<<<256 * SPLIT, 256, SMEM_BYTES>>>(R, W, b, cent, out);
}